// round 15
// baseline (speedup 1.0000x reference)
#include <cuda_runtime.h>
#include <math_constants.h>

#define B     4
#define CIN   3
#define NPTS  8192
#define COUT  64
#define KMAX  40
#define K0    10
#define K1    20
#define BN_EPS 1e-5f
#define FULL  0xFFFFFFFFu
#define WPB   8          // warps per block (topk)
#define QPW   4          // queries per warp
#define CAP   192        // candidate buffer capacity per query (E~130, >5σ)

// packed points: (x, y, z, -0.5*||p||^2)
__device__ float4 g_pts[B * NPTS];
// folded weights per (s,o): {wd0,wd1,wd2, ex,ey,ez, bias, 0}
__device__ float g_wfold[3 * COUT * 8];

// monotone float<->uint transforms (order-preserving over all finite floats)
__device__ __forceinline__ unsigned ordf(float f) {
    unsigned u = __float_as_uint(f);
    return u ^ (unsigned)(((int)u >> 31) | 0x80000000);
}
__device__ __forceinline__ float unordf(unsigned o) {
    unsigned u = (o & 0x80000000u) ? (o ^ 0x80000000u) : ~o;
    return __uint_as_float(u);
}

__device__ __forceinline__ unsigned long long u64mn(unsigned long long a, unsigned long long b) { return a < b ? a : b; }
__device__ __forceinline__ unsigned long long u64mx(unsigned long long a, unsigned long long b) { return a > b ? a : b; }
__device__ __forceinline__ unsigned u32mn(unsigned a, unsigned b) { return a < b ? a : b; }
__device__ __forceinline__ unsigned u32mx(unsigned a, unsigned b) { return a > b ? a : b; }

// ascending bitonic sort of 64 u32 keys, 2 per lane (slot lane, slot lane+32)
__device__ __forceinline__ void bitonic64_u32(unsigned &k0, unsigned &k1, int lane) {
#pragma unroll
    for (int k = 2; k <= 64; k <<= 1) {
#pragma unroll
        for (int s = 32; s > 0; s >>= 1) {
            if (s >= k) continue;
            if (s == 32) {
                unsigned lo = u32mn(k0, k1), hi = u32mx(k0, k1);
                k0 = lo; k1 = hi;
            } else {
                unsigned p0 = __shfl_xor_sync(FULL, k0, s);
                unsigned p1 = __shfl_xor_sync(FULL, k1, s);
                bool low = (lane & s) == 0;
                bool d0 = (lane & k) == 0;
                bool d1 = ((lane + 32) & k) == 0;
                k0 = (low == d0) ? u32mn(k0, p0) : u32mx(k0, p0);
                k1 = (low == d1) ? u32mn(k1, p1) : u32mx(k1, p1);
            }
        }
    }
}

// ascending bitonic sort of 64 u64 keys, 2 per lane
__device__ __forceinline__ void bitonic64_u64(unsigned long long &k0,
                                              unsigned long long &k1, int lane) {
#pragma unroll
    for (int k = 2; k <= 64; k <<= 1) {
#pragma unroll
        for (int s = 32; s > 0; s >>= 1) {
            if (s >= k) continue;
            if (s == 32) {
                unsigned long long lo = u64mn(k0, k1), hi = u64mx(k0, k1);
                k0 = lo; k1 = hi;
            } else {
                unsigned long long p0 = __shfl_xor_sync(FULL, k0, s);
                unsigned long long p1 = __shfl_xor_sync(FULL, k1, s);
                bool low = (lane & s) == 0;
                bool d0 = (lane & k) == 0;
                bool d1 = ((lane + 32) & k) == 0;
                k0 = (low == d0) ? u64mn(k0, p0) : u64mx(k0, p0);
                k1 = (low == d1) ? u64mn(k1, p1) : u64mx(k1, p1);
            }
        }
    }
}

// merge sorted-asc (k0,k1) with sorted-asc (s0,s1): keep smallest 64, sorted asc
__device__ __forceinline__ void merge64(unsigned long long &k0, unsigned long long &k1,
                                        unsigned long long s0, unsigned long long s1,
                                        int lane) {
    unsigned long long r0 = __shfl_sync(FULL, s1, 31 - lane);
    unsigned long long r1 = __shfl_sync(FULL, s0, 31 - lane);
    k0 = u64mn(k0, r0);
    k1 = u64mn(k1, r1);
    unsigned long long lo = u64mn(k0, k1), hi = u64mx(k0, k1);
    k0 = lo; k1 = hi;
#pragma unroll
    for (int s = 16; s > 0; s >>= 1) {
        unsigned long long p0 = __shfl_xor_sync(FULL, k0, s);
        unsigned long long p1 = __shfl_xor_sync(FULL, k1, s);
        bool low = (lane & s) == 0;
        k0 = low ? u64mn(k0, p0) : u64mx(k0, p0);
        k1 = low ? u64mn(k1, p1) : u64mx(k1, p1);
    }
}

// ---------------------------------------------------------------------------
// Phase 0: blocks 0..127 pack planar [B,3,N] into float4 (x,y,z,-0.5|p|^2);
//          block 128 folds BN into conv weights (192 threads).
// ---------------------------------------------------------------------------
__global__ void pack_kernel(const float* __restrict__ x,
                            const float* __restrict__ W,
                            const float* __restrict__ gamma,
                            const float* __restrict__ beta,
                            const float* __restrict__ mean,
                            const float* __restrict__ var) {
    if (blockIdx.x == (B * NPTS) / 256) {
        int so = threadIdx.x;               // s*COUT + o
        if (so < 3 * COUT) {
            const float* Ws = W + so * 6;
            float w0 = Ws[0], w1 = Ws[1], w2 = Ws[2];
            float w3 = Ws[3], w4 = Ws[4], w5 = Ws[5];
            float inv  = gamma[so] * rsqrtf(var[so] + BN_EPS);
            float bias = beta[so] - mean[so] * inv;
            float* o = g_wfold + so * 8;
            o[0] = w0 * inv; o[1] = w1 * inv; o[2] = w2 * inv;
            o[3] = (w3 - w0) * inv; o[4] = (w4 - w1) * inv; o[5] = (w5 - w2) * inv;
            o[6] = bias; o[7] = 0.f;
        }
        return;
    }
    int i = blockIdx.x * blockDim.x + threadIdx.x;   // 0 .. B*NPTS-1
    int b = i >> 13;
    int m = i & (NPTS - 1);
    const float* xb = x + (size_t)b * CIN * NPTS;
    float px = xb[m];
    float py = xb[NPTS + m];
    float pz = xb[2 * NPTS + m];
    float t = px * px;
    t = fmaf(py, py, t);
    t = fmaf(pz, pz, t);
    g_pts[i] = make_float4(px, py, pz, -0.5f * t);
}

// ---------------------------------------------------------------------------
// Fused kernel: exact top-40 (two-pass threshold select) + edge conv.
// Ranking uses w(p) = <q,p> - 0.5|p|^2, strictly monotone in -|q-p|^2.
// Pass 1 (half-sample): per-lane top-2 over even 32-blocks -> bitonic64 ->
//   40th of kept 64 = threshold (40th of ANY subset <= true 40th).
// Pass 2: accepting lanes append indices via smem atomicAdd (E~130, CAP=192).
// Epilogue per query: recompute w, sort (w desc, idx asc) == lax.top_k;
//   stash the 40 sorted neighbor float4s in the dead buf[q] smem region;
//   then compute edge conv (prefolded BN weights from smem), LeakyReLU after
//   max (monotone), and write out[s][b][o][n0..n0+3] as one float4 per (s,o)
//   (the warp's 4 queries are consecutive n).
// ---------------------------------------------------------------------------
__global__ void __launch_bounds__(32 * WPB, 4) topk_kernel(float* __restrict__ out) {
    __shared__ __align__(16) unsigned bufall[WPB * QPW * CAP];   // 24 KB
    __shared__ int cntall[WPB * QPW];                            // 128 B
    __shared__ float4 swf[3 * COUT * 2];                         // 6 KB

    const int lane = threadIdx.x & 31;
    const int warp = threadIdx.x >> 5;
    const int q0 = (blockIdx.x * WPB + warp) * QPW;   // b*NPTS + n
    const int b = q0 >> 13;                           // block stays in one batch
    const float4* __restrict__ bp = g_pts + b * NPTS;
    unsigned* buf = bufall + (size_t)warp * QPW * CAP;
    int* cnt = cntall + warp * QPW;

    {   // stage folded weights
        const float4* gw = (const float4*)g_wfold;
        for (int i = threadIdx.x; i < 3 * COUT * 2; i += 32 * WPB)
            swf[i] = gw[i];
    }
    if (lane < QPW) cnt[lane] = 0;
    __syncthreads();

    float qx[QPW], qy[QPW], qz[QPW];
#pragma unroll
    for (int q = 0; q < QPW; q++) {
        float4 Q = __ldg(&g_pts[q0 + q]);
        qx[q] = Q.x; qy[q] = Q.y; qz[q] = Q.z;
    }

    // ---- pass 1: per-lane top-2 over half-sample (even 32-blocks) ----
    float t1[QPW], t2[QPW];
#pragma unroll
    for (int q = 0; q < QPW; q++) { t1[q] = -CUDART_INF_F; t2[q] = -CUDART_INF_F; }

#pragma unroll 4
    for (int it = 0; it < NPTS; it += 64) {
        float4 p = __ldg(bp + it + lane);
#pragma unroll
        for (int q = 0; q < QPW; q++) {
            float v = fmaf(qx[q], p.x, p.w);   // p.w = -0.5|p|^2
            v = fmaf(qy[q], p.y, v);
            v = fmaf(qz[q], p.z, v);
            t2[q] = fmaxf(t2[q], fminf(v, t1[q]));  // uses old t1
            t1[q] = fmaxf(t1[q], v);
        }
    }

    float thr[QPW];
#pragma unroll
    for (int q = 0; q < QPW; q++) {
        unsigned k0 = ~ordf(t1[q]);
        unsigned k1 = ~ordf(t2[q]);
        bitonic64_u32(k0, k1, lane);
        unsigned s39 = __shfl_sync(FULL, k1, 7);   // slot 39 = 40th largest
        thr[q] = unordf(~s39);
    }

    // ---- pass 2: append indices with v >= thr (unordered, atomic) ----
#pragma unroll 4
    for (int it = 0; it < NPTS; it += 32) {
        float4 p = __ldg(bp + it + lane);
        int idx = it + lane;
#pragma unroll
        for (int q = 0; q < QPW; q++) {
            float vv = fmaf(qx[q], p.x, p.w);
            vv = fmaf(qy[q], p.y, vv);
            vv = fmaf(qz[q], p.z, vv);
            if (vv >= thr[q]) {
                int pos = atomicAdd(&cnt[q], 1);
                if (pos < CAP) buf[q * CAP + pos] = (unsigned)idx;
            }
        }
    }
    __syncwarp();

    // ---- epilogue A: per query, sort and stash sorted neighbors in smem ----
#pragma unroll 1
    for (int q = 0; q < QPW; q++) {
        unsigned* bq = buf + q * CAP;
        int c = min(cnt[q], CAP);
        const float ax = qx[q], ay = qy[q], az = qz[q];

        auto mkkey = [&](int slot) -> unsigned long long {
            if (slot >= c) return ~0ULL;
            unsigned idx = bq[slot];
            float4 p = __ldg(bp + idx);
            float v = fmaf(ax, p.x, p.w);
            v = fmaf(ay, p.y, v);
            v = fmaf(az, p.z, v);
            return (((unsigned long long)(~ordf(v))) << 13) | idx;
        };

        unsigned long long k0 = mkkey(lane);
        unsigned long long k1 = mkkey(32 + lane);
        bitonic64_u64(k0, k1, lane);
        for (int base = 64; base < c; base += 64) {
            unsigned long long s0 = mkkey(base + lane);
            unsigned long long s1 = mkkey(base + 32 + lane);
            bitonic64_u64(s0, s1, lane);
            merge64(k0, k1, s0, s1, lane);
        }
        __syncwarp();
        // overwrite the (now dead) buf[q] region with the sorted neighbors
        float4* snb_q = (float4*)((char*)bq);     // 768 B >= 640 B, 16B aligned
        snb_q[lane] = __ldg(bp + (int)(k0 & 8191u));
        if (lane < 8) snb_q[32 + lane] = __ldg(bp + (int)(k1 & 8191u));
        __syncwarp();
    }

    // ---- epilogue B: fused edge conv. lane owns channels lane, lane+32 ----
    const int n0 = q0 & (NPTS - 1);
#pragma unroll 1
    for (int oo = 0; oo < 2; oo++) {
        const int o = oo * 32 + lane;
        float wd0x, wd0y, wd0z, wd1x, wd1y, wd1z, wd2x, wd2y, wd2z;
        float ex[3], ey[3], ez[3], bb[3];
        {
            float4 a0 = swf[(0 * COUT + o) * 2], d0 = swf[(0 * COUT + o) * 2 + 1];
            float4 a1 = swf[(1 * COUT + o) * 2], d1 = swf[(1 * COUT + o) * 2 + 1];
            float4 a2 = swf[(2 * COUT + o) * 2], d2 = swf[(2 * COUT + o) * 2 + 1];
            wd0x = a0.x; wd0y = a0.y; wd0z = a0.z;
            wd1x = a1.x; wd1y = a1.y; wd1z = a1.z;
            wd2x = a2.x; wd2y = a2.y; wd2z = a2.z;
            ex[0] = a0.w; ey[0] = d0.x; ez[0] = d0.y; bb[0] = d0.z;
            ex[1] = a1.w; ey[1] = d1.x; ez[1] = d1.y; bb[1] = d1.z;
            ex[2] = a2.w; ey[2] = d2.x; ez[2] = d2.y; bb[2] = d2.z;
        }
        float r0[QPW], r1[QPW], r2[QPW];
#pragma unroll
        for (int q = 0; q < QPW; q++) {
            const float4* snb_q =
                (const float4*)((const char*)(buf + q * CAP));
            float bs0 = ex[0] * qx[q];
            bs0 = fmaf(ey[0], qy[q], bs0); bs0 = fmaf(ez[0], qz[q], bs0);
            bs0 += bb[0];
            float bs1 = ex[1] * qx[q];
            bs1 = fmaf(ey[1], qy[q], bs1); bs1 = fmaf(ez[1], qz[q], bs1);
            bs1 += bb[1];
            float bs2 = ex[2] * qx[q];
            bs2 = fmaf(ey[2], qy[q], bs2); bs2 = fmaf(ez[2], qz[q], bs2);
            bs2 += bb[2];

            float m0 = -CUDART_INF_F, m1 = -CUDART_INF_F, m2 = -CUDART_INF_F;
#pragma unroll
            for (int j = 0; j < K0; j++) {
                float4 p = snb_q[j];
                float v0 = fmaf(wd0x, p.x, bs0);
                v0 = fmaf(wd0y, p.y, v0); v0 = fmaf(wd0z, p.z, v0);
                m0 = fmaxf(m0, v0);
                float v1 = fmaf(wd1x, p.x, bs1);
                v1 = fmaf(wd1y, p.y, v1); v1 = fmaf(wd1z, p.z, v1);
                m1 = fmaxf(m1, v1);
                float v2 = fmaf(wd2x, p.x, bs2);
                v2 = fmaf(wd2y, p.y, v2); v2 = fmaf(wd2z, p.z, v2);
                m2 = fmaxf(m2, v2);
            }
#pragma unroll
            for (int j = K0; j < K1; j++) {
                float4 p = snb_q[j];
                float v1 = fmaf(wd1x, p.x, bs1);
                v1 = fmaf(wd1y, p.y, v1); v1 = fmaf(wd1z, p.z, v1);
                m1 = fmaxf(m1, v1);
                float v2 = fmaf(wd2x, p.x, bs2);
                v2 = fmaf(wd2y, p.y, v2); v2 = fmaf(wd2z, p.z, v2);
                m2 = fmaxf(m2, v2);
            }
#pragma unroll
            for (int j = K1; j < KMAX; j++) {
                float4 p = snb_q[j];
                float v2 = fmaf(wd2x, p.x, bs2);
                v2 = fmaf(wd2y, p.y, v2); v2 = fmaf(wd2z, p.z, v2);
                m2 = fmaxf(m2, v2);
            }
            r0[q] = fmaxf(m0, 0.2f * m0);   // LeakyReLU after max (monotone)
            r1[q] = fmaxf(m1, 0.2f * m1);
            r2[q] = fmaxf(m2, 0.2f * m2);
        }
        const size_t stride = (size_t)B * COUT * NPTS;
        size_t basep = ((size_t)b * COUT + o) * NPTS + n0;
        *(float4*)(out + basep) =
            make_float4(r0[0], r0[1], r0[2], r0[3]);
        *(float4*)(out + basep + stride) =
            make_float4(r1[0], r1[1], r1[2], r1[3]);
        *(float4*)(out + basep + 2 * stride) =
            make_float4(r2[0], r2[1], r2[2], r2[3]);
    }
}

extern "C" void kernel_launch(void* const* d_in, const int* in_sizes, int n_in,
                              void* d_out, int out_size) {
    const float* x     = (const float*)d_in[0];
    const float* W     = (const float*)d_in[1];
    const float* gamma = (const float*)d_in[2];
    const float* beta  = (const float*)d_in[3];
    const float* mean  = (const float*)d_in[4];
    const float* var   = (const float*)d_in[5];
    float* out = (float*)d_out;

    pack_kernel<<<(B * NPTS) / 256 + 1, 256>>>(x, W, gamma, beta, mean, var);
    topk_kernel<<<(B * NPTS) / (QPW * WPB), 32 * WPB>>>(out);
}

// round 16
// speedup vs baseline: 2.2147x; 2.2147x over previous
#include <cuda_runtime.h>
#include <math_constants.h>

#define B     4
#define CIN   3
#define NPTS  8192
#define COUT  64
#define KMAX  40
#define K0    10
#define K1    20
#define BN_EPS 1e-5f
#define FULL  0xFFFFFFFFu
#define WPB   8          // warps per block (topk)
#define QPW   4          // queries per warp
#define CAP   192        // candidate buffer capacity per query (E~130, >5σ)
#define EPTS  4          // points per block (edgeconv)

// packed points: (x, y, z, -0.5*||p||^2)
__device__ float4 g_pts[B * NPTS];
// gathered neighbor coords per (b,n): 40 float4, sorted by descending dist
__device__ float4 g_nb[(size_t)B * NPTS * KMAX];
// folded weights per (s,o): {wd0,wd1,wd2, ex,ey,ez, bias, 0}
__device__ float g_wfold[3 * COUT * 8];

// monotone float<->uint transforms (order-preserving over all finite floats)
__device__ __forceinline__ unsigned ordf(float f) {
    unsigned u = __float_as_uint(f);
    return u ^ (unsigned)(((int)u >> 31) | 0x80000000);
}
__device__ __forceinline__ float unordf(unsigned o) {
    unsigned u = (o & 0x80000000u) ? (o ^ 0x80000000u) : ~o;
    return __uint_as_float(u);
}

__device__ __forceinline__ unsigned long long u64mn(unsigned long long a, unsigned long long b) { return a < b ? a : b; }
__device__ __forceinline__ unsigned long long u64mx(unsigned long long a, unsigned long long b) { return a > b ? a : b; }
__device__ __forceinline__ unsigned u32mn(unsigned a, unsigned b) { return a < b ? a : b; }
__device__ __forceinline__ unsigned u32mx(unsigned a, unsigned b) { return a > b ? a : b; }

// ascending bitonic sort of 64 u32 keys, 2 per lane (slot lane, slot lane+32)
__device__ __forceinline__ void bitonic64_u32(unsigned &k0, unsigned &k1, int lane) {
#pragma unroll
    for (int k = 2; k <= 64; k <<= 1) {
#pragma unroll
        for (int s = 32; s > 0; s >>= 1) {
            if (s >= k) continue;
            if (s == 32) {
                unsigned lo = u32mn(k0, k1), hi = u32mx(k0, k1);
                k0 = lo; k1 = hi;
            } else {
                unsigned p0 = __shfl_xor_sync(FULL, k0, s);
                unsigned p1 = __shfl_xor_sync(FULL, k1, s);
                bool low = (lane & s) == 0;
                bool d0 = (lane & k) == 0;
                bool d1 = ((lane + 32) & k) == 0;
                k0 = (low == d0) ? u32mn(k0, p0) : u32mx(k0, p0);
                k1 = (low == d1) ? u32mn(k1, p1) : u32mx(k1, p1);
            }
        }
    }
}

// ascending bitonic sort of 64 u64 keys, 2 per lane
__device__ __forceinline__ void bitonic64_u64(unsigned long long &k0,
                                              unsigned long long &k1, int lane) {
#pragma unroll
    for (int k = 2; k <= 64; k <<= 1) {
#pragma unroll
        for (int s = 32; s > 0; s >>= 1) {
            if (s >= k) continue;
            if (s == 32) {
                unsigned long long lo = u64mn(k0, k1), hi = u64mx(k0, k1);
                k0 = lo; k1 = hi;
            } else {
                unsigned long long p0 = __shfl_xor_sync(FULL, k0, s);
                unsigned long long p1 = __shfl_xor_sync(FULL, k1, s);
                bool low = (lane & s) == 0;
                bool d0 = (lane & k) == 0;
                bool d1 = ((lane + 32) & k) == 0;
                k0 = (low == d0) ? u64mn(k0, p0) : u64mx(k0, p0);
                k1 = (low == d1) ? u64mn(k1, p1) : u64mx(k1, p1);
            }
        }
    }
}

// merge sorted-asc (k0,k1) with sorted-asc (s0,s1): keep smallest 64, sorted asc
__device__ __forceinline__ void merge64(unsigned long long &k0, unsigned long long &k1,
                                        unsigned long long s0, unsigned long long s1,
                                        int lane) {
    unsigned long long r0 = __shfl_sync(FULL, s1, 31 - lane);
    unsigned long long r1 = __shfl_sync(FULL, s0, 31 - lane);
    k0 = u64mn(k0, r0);
    k1 = u64mn(k1, r1);
    unsigned long long lo = u64mn(k0, k1), hi = u64mx(k0, k1);
    k0 = lo; k1 = hi;
#pragma unroll
    for (int s = 16; s > 0; s >>= 1) {
        unsigned long long p0 = __shfl_xor_sync(FULL, k0, s);
        unsigned long long p1 = __shfl_xor_sync(FULL, k1, s);
        bool low = (lane & s) == 0;
        k0 = low ? u64mn(k0, p0) : u64mx(k0, p0);
        k1 = low ? u64mn(k1, p1) : u64mx(k1, p1);
    }
}

// ---------------------------------------------------------------------------
// Phase 0: blocks 0..127 pack planar [B,3,N] into float4 (x,y,z,-0.5|p|^2);
//          block 128 folds BN into conv weights (192 threads).
// ---------------------------------------------------------------------------
__global__ void pack_kernel(const float* __restrict__ x,
                            const float* __restrict__ W,
                            const float* __restrict__ gamma,
                            const float* __restrict__ beta,
                            const float* __restrict__ mean,
                            const float* __restrict__ var) {
    if (blockIdx.x == (B * NPTS) / 256) {
        int so = threadIdx.x;               // s*COUT + o
        if (so < 3 * COUT) {
            const float* Ws = W + so * 6;
            float w0 = Ws[0], w1 = Ws[1], w2 = Ws[2];
            float w3 = Ws[3], w4 = Ws[4], w5 = Ws[5];
            float inv  = gamma[so] * rsqrtf(var[so] + BN_EPS);
            float bias = beta[so] - mean[so] * inv;
            float* o = g_wfold + so * 8;
            o[0] = w0 * inv; o[1] = w1 * inv; o[2] = w2 * inv;
            o[3] = (w3 - w0) * inv; o[4] = (w4 - w1) * inv; o[5] = (w5 - w2) * inv;
            o[6] = bias; o[7] = 0.f;
        }
        return;
    }
    int i = blockIdx.x * blockDim.x + threadIdx.x;   // 0 .. B*NPTS-1
    int b = i >> 13;
    int m = i & (NPTS - 1);
    const float* xb = x + (size_t)b * CIN * NPTS;
    float px = xb[m];
    float py = xb[NPTS + m];
    float pz = xb[2 * NPTS + m];
    float t = px * px;
    t = fmaf(py, py, t);
    t = fmaf(pz, pz, t);
    g_pts[i] = make_float4(px, py, pz, -0.5f * t);
}

// ---------------------------------------------------------------------------
// Phase 1: two-pass exact top-40, 4 queries per warp, candidates via L1.
// Ranking uses w(p) = <q,p> - 0.5|p|^2, a strictly monotone per-query
// transform of -|q-p|^2: identical neighbor ordering.
// Pass 1 (HALF-SAMPLE): per-lane top-2 over the even 32-blocks (4096 pts)
//         -> bitonic64 -> 40th of the kept 64 sample elements = threshold.
//         40th-largest of ANY stream subset <= true 40th => conservative.
// Pass 2: accepting lanes append their INDEX to a per-query smem buffer via
//         atomicAdd (no ballots; buffer order irrelevant). E[count]~130,
//         CAP=192 (>5σ). smem = 24 KB/CTA so 4 CTAs leave >=128 KB L1
//         carveout for the point set (R15 showed exceeding this is a cliff).
// Epilogue: recompute w for survivors (identical expression => bit-equal),
//         sort keys (~ord(w)<<13 | idx) == (w desc, idx asc) == lax.top_k
//         order; gather neighbor float4s to g_nb (coalesced edgeconv read).
// ---------------------------------------------------------------------------
__global__ void __launch_bounds__(32 * WPB, 4) topk_kernel() {
    __shared__ unsigned bufall[WPB * QPW * CAP];   // 24 KB
    __shared__ int cntall[WPB * QPW];              // 128 B

    const int lane = threadIdx.x & 31;
    const int warp = threadIdx.x >> 5;
    const int q0 = (blockIdx.x * WPB + warp) * QPW;   // b*NPTS + n
    const int b = q0 >> 13;                           // block stays in one batch
    const float4* __restrict__ bp = g_pts + b * NPTS;
    unsigned* buf = bufall + (size_t)warp * QPW * CAP;
    int* cnt = cntall + warp * QPW;

    if (lane < QPW) cnt[lane] = 0;
    __syncwarp();

    float qx[QPW], qy[QPW], qz[QPW];
#pragma unroll
    for (int q = 0; q < QPW; q++) {
        float4 Q = __ldg(&g_pts[q0 + q]);
        qx[q] = Q.x; qy[q] = Q.y; qz[q] = Q.z;
    }

    // ---- pass 1: per-lane top-2 over half-sample (even 32-blocks) ----
    float t1[QPW], t2[QPW];
#pragma unroll
    for (int q = 0; q < QPW; q++) { t1[q] = -CUDART_INF_F; t2[q] = -CUDART_INF_F; }

#pragma unroll 4
    for (int it = 0; it < NPTS; it += 64) {
        float4 p = __ldg(bp + it + lane);
#pragma unroll
        for (int q = 0; q < QPW; q++) {
            float v = fmaf(qx[q], p.x, p.w);   // p.w = -0.5|p|^2
            v = fmaf(qy[q], p.y, v);
            v = fmaf(qz[q], p.z, v);
            t2[q] = fmaxf(t2[q], fminf(v, t1[q]));  // uses old t1
            t1[q] = fmaxf(t1[q], v);
        }
    }

    float thr[QPW];
#pragma unroll
    for (int q = 0; q < QPW; q++) {
        unsigned k0 = ~ordf(t1[q]);
        unsigned k1 = ~ordf(t2[q]);
        bitonic64_u32(k0, k1, lane);
        unsigned s39 = __shfl_sync(FULL, k1, 7);   // slot 39 = 40th largest
        thr[q] = unordf(~s39);
    }

    // ---- pass 2: append indices with v >= thr (unordered, atomic) ----
#pragma unroll 4
    for (int it = 0; it < NPTS; it += 32) {
        float4 p = __ldg(bp + it + lane);
        int idx = it + lane;
#pragma unroll
        for (int q = 0; q < QPW; q++) {
            float vv = fmaf(qx[q], p.x, p.w);
            vv = fmaf(qy[q], p.y, vv);
            vv = fmaf(qz[q], p.z, vv);
            if (vv >= thr[q]) {
                int pos = atomicAdd(&cnt[q], 1);
                if (pos < CAP) buf[q * CAP + pos] = (unsigned)idx;
            }
        }
    }
    __syncwarp();

    // ---- epilogue: recompute w, sort, select top-40, gather ----
#pragma unroll 1
    for (int q = 0; q < QPW; q++) {
        unsigned* bq = buf + q * CAP;
        int c = min(cnt[q], CAP);
        const float ax = qx[q], ay = qy[q], az = qz[q];

        auto mkkey = [&](int slot) -> unsigned long long {
            if (slot >= c) return ~0ULL;
            unsigned idx = bq[slot];
            float4 p = __ldg(bp + idx);
            float v = fmaf(ax, p.x, p.w);
            v = fmaf(ay, p.y, v);
            v = fmaf(az, p.z, v);
            return (((unsigned long long)(~ordf(v))) << 13) | idx;
        };

        unsigned long long k0 = mkkey(lane);
        unsigned long long k1 = mkkey(32 + lane);
        bitonic64_u64(k0, k1, lane);
        for (int base = 64; base < c; base += 64) {
            unsigned long long s0 = mkkey(base + lane);
            unsigned long long s1 = mkkey(base + 32 + lane);
            bitonic64_u64(s0, s1, lane);
            merge64(k0, k1, s0, s1, lane);
        }
        float4* o = g_nb + (size_t)(q0 + q) * KMAX;
        o[lane] = __ldg(bp + (int)(k0 & 8191u));
        if (lane < 8) o[32 + lane] = __ldg(bp + (int)(k1 & 8191u));
    }
}

// ---------------------------------------------------------------------------
// Phase 2: edge conv with pre-folded BN weights + LeakyReLU (after max) + max.
// 256 threads = 4 points x 64 channels; neighbors streamed coalesced from
// g_nb; output staged in smem, written as coalesced float4 (4 consecutive n).
// ---------------------------------------------------------------------------
__global__ void __launch_bounds__(64 * EPTS) edgeconv_kernel(float* __restrict__ out)
{
    __shared__ float4 snb[EPTS][KMAX];
    __shared__ float  sres[3][EPTS][COUT];

    const int t = threadIdx.x;
    const int grp = t >> 6, o = t & 63;
    const int bn0 = blockIdx.x * EPTS;
    const int bn = bn0 + grp;
    const int b = bn >> 13;                     // all 4 points same batch

    if (o < KMAX) snb[grp][o] = g_nb[(size_t)bn * KMAX + o];
    const float4 c = g_pts[bn];
    __syncthreads();

    const float cx = c.x, cy = c.y, cz = c.z;

    float wd[3][3], basec[3];
#pragma unroll
    for (int s = 0; s < 3; s++) {
        const float* wf = g_wfold + (s * COUT + o) * 8;
        float4 a = *(const float4*)wf;       // wd0, wd1, wd2, ex
        float4 d = *(const float4*)(wf + 4); // ey, ez, bias, 0
        wd[s][0] = a.x; wd[s][1] = a.y; wd[s][2] = a.z;
        float bse = a.w * cx;
        bse = fmaf(d.x, cy, bse);
        bse = fmaf(d.y, cz, bse);
        basec[s] = bse + d.z;
    }

    float m0 = -CUDART_INF_F, m1 = -CUDART_INF_F, m2 = -CUDART_INF_F;
#pragma unroll
    for (int j = 0; j < K0; j++) {
        float4 p = snb[grp][j];
        float t0 = fmaf(wd[0][0], p.x, basec[0]);
        t0 = fmaf(wd[0][1], p.y, t0); t0 = fmaf(wd[0][2], p.z, t0);
        m0 = fmaxf(m0, t0);
        float t1 = fmaf(wd[1][0], p.x, basec[1]);
        t1 = fmaf(wd[1][1], p.y, t1); t1 = fmaf(wd[1][2], p.z, t1);
        m1 = fmaxf(m1, t1);
        float t2 = fmaf(wd[2][0], p.x, basec[2]);
        t2 = fmaf(wd[2][1], p.y, t2); t2 = fmaf(wd[2][2], p.z, t2);
        m2 = fmaxf(m2, t2);
    }
#pragma unroll
    for (int j = K0; j < K1; j++) {
        float4 p = snb[grp][j];
        float t1 = fmaf(wd[1][0], p.x, basec[1]);
        t1 = fmaf(wd[1][1], p.y, t1); t1 = fmaf(wd[1][2], p.z, t1);
        m1 = fmaxf(m1, t1);
        float t2 = fmaf(wd[2][0], p.x, basec[2]);
        t2 = fmaf(wd[2][1], p.y, t2); t2 = fmaf(wd[2][2], p.z, t2);
        m2 = fmaxf(m2, t2);
    }
#pragma unroll
    for (int j = K1; j < KMAX; j++) {
        float4 p = snb[grp][j];
        float t2 = fmaf(wd[2][0], p.x, basec[2]);
        t2 = fmaf(wd[2][1], p.y, t2); t2 = fmaf(wd[2][2], p.z, t2);
        m2 = fmaxf(m2, t2);
    }

    m0 = fmaxf(m0, 0.2f * m0);
    m1 = fmaxf(m1, 0.2f * m1);
    m2 = fmaxf(m2, 0.2f * m2);

    sres[0][grp][o] = m0;
    sres[1][grp][o] = m1;
    sres[2][grp][o] = m2;
    __syncthreads();

    if (t < 192) {
        int s = t >> 6, oo = t & 63;
        float4 vv = make_float4(sres[s][0][oo], sres[s][1][oo],
                                sres[s][2][oo], sres[s][3][oo]);
        const int n0 = bn0 & (NPTS - 1);
        size_t basep = ((size_t)s * B * COUT + (size_t)b * COUT + oo) * NPTS + n0;
        *(float4*)(out + basep) = vv;
    }
}

extern "C" void kernel_launch(void* const* d_in, const int* in_sizes, int n_in,
                              void* d_out, int out_size) {
    const float* x     = (const float*)d_in[0];
    const float* W     = (const float*)d_in[1];
    const float* gamma = (const float*)d_in[2];
    const float* beta  = (const float*)d_in[3];
    const float* mean  = (const float*)d_in[4];
    const float* var   = (const float*)d_in[5];
    float* out = (float*)d_out;

    pack_kernel<<<(B * NPTS) / 256 + 1, 256>>>(x, W, gamma, beta, mean, var);
    topk_kernel<<<(B * NPTS) / (QPW * WPB), 32 * WPB>>>();
    edgeconv_kernel<<<(B * NPTS) / EPTS, 64 * EPTS>>>(out);
}